// round 13
// baseline (speedup 1.0000x reference)
#include <cuda_runtime.h>
#include <cstdint>

#define NNODES 50000
#define NEDGES 800000
#define HID 128

#define SB 512
#define SNB ((NNODES + SB - 1) / SB)  // 98

__device__ float g_agg[(size_t)NNODES * HID];
__device__ float g_colsum[HID];
__device__ float g_b1adj[HID];
__device__ int g_is64;              // 1 if edge_index is int64
__device__ int g_deg[NNODES];       // receiver degree histogram
__device__ int g_off[NNODES];       // exclusive-scan start offsets
__device__ int g_cursor[NNODES];    // fill cursors
__device__ int g_perm[NEDGES];      // edge ids grouped by receiver
__device__ int g_bsum[SNB];         // scan block sums

// ---------------------------------------------------------------------------
// Fused: detect edge_index dtype (block 0) + zero g_deg/g_colsum.
// ---------------------------------------------------------------------------
__global__ void init_kernel(const int* __restrict__ ei32) {
    if (blockIdx.x == 0) {
        __shared__ int nz;
        if (threadIdx.x == 0) nz = 0;
        __syncthreads();
        int cnt = 0;
        for (int i = threadIdx.x; i < 1024; i += blockDim.x)
            if (ei32[2 * i + 1] != 0) cnt++;
        atomicAdd(&nz, cnt);
        __syncthreads();
        if (threadIdx.x == 0) g_is64 = (nz == 0) ? 1 : 0;
        if (threadIdx.x < HID) g_colsum[threadIdx.x] = 0.0f;
    }
    for (int i = blockIdx.x * blockDim.x + threadIdx.x; i < NNODES;
         i += gridDim.x * blockDim.x)
        g_deg[i] = 0;
}

// ---------------------------------------------------------------------------
// Fused: edge_index -> float passthrough + receiver histogram.
// ---------------------------------------------------------------------------
__global__ void eidx_hist_kernel(const void* __restrict__ ei,
                                 float* __restrict__ out) {
    int total = 2 * NEDGES;
    for (int i = blockIdx.x * blockDim.x + threadIdx.x; i < total;
         i += gridDim.x * blockDim.x) {
        long long v;
        if (g_is64)
            v = ((const long long*)ei)[i];
        else
            v = ((const int*)ei)[i];
        if (out) out[i] = (float)v;
        if (i >= NEDGES && v >= 0 && v < NNODES)
            atomicAdd(&g_deg[(int)v], 1);
    }
}

// ---------------------------------------------------------------------------
// Device-wide exclusive scan, 3 phases.
// ---------------------------------------------------------------------------
__global__ void __launch_bounds__(SB) scan1_kernel() {
    __shared__ int s[SB];
    const int b = blockIdx.x, t = threadIdx.x;
    const int i = b * SB + t;
    int v = (i < NNODES) ? g_deg[i] : 0;
    s[t] = v;
    __syncthreads();
    for (int d = 1; d < SB; d <<= 1) {
        int x = (t >= d) ? s[t - d] : 0;
        __syncthreads();
        s[t] += x;
        __syncthreads();
    }
    if (i < NNODES) g_off[i] = s[t] - v;
    if (t == SB - 1) g_bsum[b] = s[t];
}

__global__ void __launch_bounds__(128) scan2_kernel() {
    __shared__ int sh[128];
    const int t = threadIdx.x;
    int v = (t < SNB) ? g_bsum[t] : 0;
    sh[t] = v;
    __syncthreads();
    for (int d = 1; d < 128; d <<= 1) {
        int x = (t >= d) ? sh[t - d] : 0;
        __syncthreads();
        sh[t] += x;
        __syncthreads();
    }
    if (t < SNB) g_bsum[t] = sh[t] - v;
}

__global__ void __launch_bounds__(SB) scan3_kernel() {
    const int b = blockIdx.x, t = threadIdx.x;
    const int i = b * SB + t;
    if (i < NNODES) {
        int o = g_off[i] + g_bsum[b];
        g_off[i] = o;
        g_cursor[i] = o;
    }
}

// ---------------------------------------------------------------------------
// Fill permutation: group edge ids by receiver.
// ---------------------------------------------------------------------------
__global__ void fill_kernel(const void* __restrict__ ei) {
    for (int e = blockIdx.x * blockDim.x + threadIdx.x; e < NEDGES;
         e += gridDim.x * blockDim.x) {
        long long v;
        if (g_is64)
            v = ((const long long*)ei)[(size_t)NEDGES + e];
        else
            v = ((const int*)ei)[(size_t)NEDGES + e];
        if (v < 0 || v >= NNODES) continue;
        int pos = atomicAdd(&g_cursor[(int)v], 1);
        g_perm[pos] = e;
    }
}

// ---------------------------------------------------------------------------
// Gather: one warp per node; no float atomics; fused passthrough + colsum.
// ---------------------------------------------------------------------------
__global__ void __launch_bounds__(256) gather_kernel(
    const float* __restrict__ edge_attr,
    float* __restrict__ out_edge_attr) {
    __shared__ float s_cs[HID];
    const int t = threadIdx.x;
    if (t < HID) s_cs[t] = 0.0f;
    __syncthreads();

    const int lane = t & 31;
    const int node = blockIdx.x * 8 + (t >> 5);

    float4 acc = make_float4(0.f, 0.f, 0.f, 0.f);
    if (node < NNODES) {
        const int start = g_off[node];
        const int deg = g_deg[node];
        int i = 0;
        for (; i + 2 <= deg; i += 2) {
            int e0 = g_perm[start + i];
            int e1 = g_perm[start + i + 1];
            float4 v0 = ((const float4*)(edge_attr + (size_t)e0 * HID))[lane];
            float4 v1 = ((const float4*)(edge_attr + (size_t)e1 * HID))[lane];
            if (out_edge_attr) {
                ((float4*)(out_edge_attr + (size_t)e0 * HID))[lane] = v0;
                ((float4*)(out_edge_attr + (size_t)e1 * HID))[lane] = v1;
            }
            acc.x += v0.x + v1.x;
            acc.y += v0.y + v1.y;
            acc.z += v0.z + v1.z;
            acc.w += v0.w + v1.w;
        }
        if (i < deg) {
            int e0 = g_perm[start + i];
            float4 v0 = ((const float4*)(edge_attr + (size_t)e0 * HID))[lane];
            if (out_edge_attr)
                ((float4*)(out_edge_attr + (size_t)e0 * HID))[lane] = v0;
            acc.x += v0.x;
            acc.y += v0.y;
            acc.z += v0.z;
            acc.w += v0.w;
        }
        ((float4*)(g_agg + (size_t)node * HID))[lane] = acc;
    }

    atomicAdd(&s_cs[lane * 4 + 0], acc.x);
    atomicAdd(&s_cs[lane * 4 + 1], acc.y);
    atomicAdd(&s_cs[lane * 4 + 2], acc.z);
    atomicAdd(&s_cs[lane * 4 + 3], acc.w);
    __syncthreads();
    if (t < 32) {
        float4 cv = *(float4*)&s_cs[t * 4];
        asm volatile("red.global.add.v4.f32 [%0], {%1, %2, %3, %4};"
                     :: "l"(&g_colsum[t * 4]), "f"(cv.x), "f"(cv.y), "f"(cv.z),
                        "f"(cv.w)
                     : "memory");
    }
}

// b1'[j] = b1[j] - (1/N) * sum_c colsum[c] * W1[128+c][j]
__global__ void b1adj_kernel(const float* __restrict__ W1,
                             const float* __restrict__ b1) {
    int j = threadIdx.x;
    float acc = 0.0f;
#pragma unroll 8
    for (int c = 0; c < HID; c++)
        acc = fmaf(g_colsum[c], W1[(size_t)(HID + c) * HID + j], acc);
    g_b1adj[j] = b1[j] - acc * (1.0f / (float)NNODES);
}

// ---------------------------------------------------------------------------
// Fused MLP with cp.async double buffering.
// Phase 1: h = relu([node_attr|agg] @ W1 + b1') -> smem Hs (tf32).
// Phase 2: x = h @ W2 + b2 -> out.
// Smem: 2x As (18KB) + 2x Bs (16.5KB) + Hs (66KB) = 135KB, 1 CTA/SM.
// tf32 cvt moved to fragment-load time (off critical path).
// ---------------------------------------------------------------------------
__device__ __forceinline__ float f2tf(float x) {
    uint32_t r;
    asm("cvt.rna.tf32.f32 %0, %1;" : "=r"(r) : "f"(x));
    return __uint_as_float(r);
}

__device__ __forceinline__ uint32_t tfbits(float x) {
    uint32_t r;
    asm("cvt.rna.tf32.f32 %0, %1;" : "=r"(r) : "f"(x));
    return r;
}

__device__ __forceinline__ void mma_tf32(float* c, const uint32_t* a,
                                         const uint32_t* b) {
    asm volatile(
        "mma.sync.aligned.m16n8k8.row.col.f32.tf32.tf32.f32 "
        "{%0,%1,%2,%3}, {%4,%5,%6,%7}, {%8,%9}, {%0,%1,%2,%3};"
        : "+f"(c[0]), "+f"(c[1]), "+f"(c[2]), "+f"(c[3])
        : "r"(a[0]), "r"(a[1]), "r"(a[2]), "r"(a[3]), "r"(b[0]), "r"(b[1]));
}

__device__ __forceinline__ void cp16(uint32_t dst_smem, const void* src,
                                     int src_sz) {
    asm volatile("cp.async.cg.shared.global [%0], [%1], 16, %2;"
                 :: "r"(dst_smem), "l"(src), "r"(src_sz));
}
#define CP_COMMIT() asm volatile("cp.async.commit_group;")
#define CP_WAIT(N) asm volatile("cp.async.wait_group %0;" :: "n"(N))

// smem layout (floats)
#define AS_OFF(b) ((b) * 4608)            // 128*36 each
#define BS_OFF(b) (9216 + (b) * 4224)     // 32*132 each
#define HS_OFF 17664                      // 128*132
#define SMEM_FLOATS (17664 + 128 * 132)   // 34560 -> 138240 B

__global__ void __launch_bounds__(256) mlp_fused_kernel(
    const float* __restrict__ A0, const float* __restrict__ A1,
    const float* __restrict__ W1, const float* __restrict__ bias1,
    const float* __restrict__ W2, const float* __restrict__ bias2,
    float* __restrict__ C) {
    extern __shared__ float smem[];
    const uint32_t sbase = (uint32_t)__cvta_generic_to_shared(smem);

    const int t = threadIdx.x;
    const int w = t >> 5, lane = t & 31;
    const int wm = w >> 2, wn = w & 3;
    const int g = lane >> 2, j = lane & 3;
    const int block_m = blockIdx.x * 128;

    // per-thread load coordinates
    const int a_row = t >> 3;             // 0..31 (x4 iters covers 128)
    const int a_c4 = (t & 7) * 4;
    const int b_kr = t >> 5;              // 0..7 (x4 iters covers 32)
    const int b_c4 = (t & 31) * 4;

    // ---- issue helpers (phase 1) ----
    auto issue_p1 = [&](int kb, int bi) {
        const int kbase = kb * 32;
#pragma unroll
        for (int i = 0; i < 4; i++) {
            int row = a_row + i * 32;
            int gm = block_m + row;
            int k = kbase + a_c4;
            const float* src = (k < HID) ? (A0 + (size_t)gm * HID + k)
                                         : (A1 + (size_t)gm * HID + (k - HID));
            cp16(sbase + (AS_OFF(bi) + row * 36 + a_c4) * 4, src,
                 (gm < NNODES) ? 16 : 0);
        }
#pragma unroll
        for (int i = 0; i < 4; i++) {
            int kr = b_kr + i * 8;
            cp16(sbase + (BS_OFF(bi) + kr * 132 + b_c4) * 4,
                 W1 + (size_t)(kbase + kr) * HID + b_c4, 16);
        }
        CP_COMMIT();
    };

    float(*Hs)[132] = (float(*)[132])(smem + HS_OFF);

    // ===== Phase 1: K=256, 8 k-blocks, double-buffered =====
    {
        float acc[4][4][4] = {};
        issue_p1(0, 0);
        for (int kb = 0; kb < 8; kb++) {
            const int bi = kb & 1;
            if (kb + 1 < 8) {
                issue_p1(kb + 1, (kb + 1) & 1);
                CP_WAIT(1);
            } else {
                CP_WAIT(0);
            }
            __syncthreads();

            const float* As = smem + AS_OFF(bi);
            const float* Bs = smem + BS_OFF(bi);
#pragma unroll
            for (int kk = 0; kk < 4; kk++) {
                const int k0 = kk * 8;
                uint32_t bf[4][2];
#pragma unroll
                for (int nt = 0; nt < 4; nt++) {
                    int n0 = wn * 32 + nt * 8 + g;
                    bf[nt][0] = tfbits(Bs[(k0 + j) * 132 + n0]);
                    bf[nt][1] = tfbits(Bs[(k0 + j + 4) * 132 + n0]);
                }
#pragma unroll
                for (int mt = 0; mt < 4; mt++) {
                    int m0 = wm * 64 + mt * 16;
                    uint32_t af[4];
                    af[0] = tfbits(As[(m0 + g) * 36 + k0 + j]);
                    af[1] = tfbits(As[(m0 + g + 8) * 36 + k0 + j]);
                    af[2] = tfbits(As[(m0 + g) * 36 + k0 + j + 4]);
                    af[3] = tfbits(As[(m0 + g + 8) * 36 + k0 + j + 4]);
#pragma unroll
                    for (int nt = 0; nt < 4; nt++)
                        mma_tf32(acc[mt][nt], af, bf[nt]);
                }
            }
            __syncthreads();
        }

        // epilogue 1: bias + relu + tf32 -> Hs
#pragma unroll
        for (int mt = 0; mt < 4; mt++) {
#pragma unroll
            for (int half = 0; half < 2; half++) {
                int row = wm * 64 + mt * 16 + g + half * 8;
#pragma unroll
                for (int nt = 0; nt < 4; nt++) {
                    int n = wn * 32 + nt * 8 + 2 * j;
                    float x0 = acc[mt][nt][half * 2 + 0] + bias1[n + 0];
                    float x1 = acc[mt][nt][half * 2 + 1] + bias1[n + 1];
                    Hs[row][n] = f2tf(fmaxf(x0, 0.f));
                    Hs[row][n + 1] = f2tf(fmaxf(x1, 0.f));
                }
            }
        }
        __syncthreads();
    }

    // ---- issue helper (phase 2: W2 tiles only) ----
    auto issue_p2 = [&](int kb, int bi) {
        const int kbase = kb * 32;
#pragma unroll
        for (int i = 0; i < 4; i++) {
            int kr = b_kr + i * 8;
            cp16(sbase + (BS_OFF(bi) + kr * 132 + b_c4) * 4,
                 W2 + (size_t)(kbase + kr) * HID + b_c4, 16);
        }
        CP_COMMIT();
    };

    // ===== Phase 2: K=128, 4 k-blocks, A from Hs =====
    {
        float acc[4][4][4] = {};
        issue_p2(0, 0);
        for (int kb = 0; kb < 4; kb++) {
            const int bi = kb & 1;
            if (kb + 1 < 4) {
                issue_p2(kb + 1, (kb + 1) & 1);
                CP_WAIT(1);
            } else {
                CP_WAIT(0);
            }
            __syncthreads();

            const float* Bs = smem + BS_OFF(bi);
            const int kbase = kb * 32;
#pragma unroll
            for (int kk = 0; kk < 4; kk++) {
                const int k0 = kbase + kk * 8;
                uint32_t bf[4][2];
#pragma unroll
                for (int nt = 0; nt < 4; nt++) {
                    int n0 = wn * 32 + nt * 8 + g;
                    bf[nt][0] = tfbits(Bs[(kk * 8 + j) * 132 + n0]);
                    bf[nt][1] = tfbits(Bs[(kk * 8 + j + 4) * 132 + n0]);
                }
#pragma unroll
                for (int mt = 0; mt < 4; mt++) {
                    int m0 = wm * 64 + mt * 16;
                    uint32_t af[4];
                    af[0] = __float_as_uint(Hs[m0 + g][k0 + j]);
                    af[1] = __float_as_uint(Hs[m0 + g + 8][k0 + j]);
                    af[2] = __float_as_uint(Hs[m0 + g][k0 + j + 4]);
                    af[3] = __float_as_uint(Hs[m0 + g + 8][k0 + j + 4]);
#pragma unroll
                    for (int nt = 0; nt < 4; nt++)
                        mma_tf32(acc[mt][nt], af, bf[nt]);
                }
            }
            __syncthreads();
        }

        // epilogue 2: bias, store
#pragma unroll
        for (int mt = 0; mt < 4; mt++) {
#pragma unroll
            for (int half = 0; half < 2; half++) {
                int gm = block_m + wm * 64 + mt * 16 + g + half * 8;
                if (gm >= NNODES) continue;
#pragma unroll
                for (int nt = 0; nt < 4; nt++) {
                    int n = wn * 32 + nt * 8 + 2 * j;
                    float2 v;
                    v.x = acc[mt][nt][half * 2 + 0] + bias2[n + 0];
                    v.y = acc[mt][nt][half * 2 + 1] + bias2[n + 1];
                    *(float2*)(C + (size_t)gm * HID + n) = v;
                }
            }
        }
    }
}

extern "C" void kernel_launch(void* const* d_in, const int* in_sizes, int n_in,
                              void* d_out, int out_size) {
    const float* node_attr = (const float*)d_in[0];
    const void* edge_index = d_in[1];
    const float* edge_attr = (const float*)d_in[2];
    const float* W1 = (const float*)d_in[3];
    const float* b1 = (const float*)d_in[4];
    const float* W2 = (const float*)d_in[5];
    const float* b2 = (const float*)d_in[6];
    float* out = (float*)d_out;

    float *s_agg, *s_b1adj;
    cudaGetSymbolAddress((void**)&s_agg, g_agg);
    cudaGetSymbolAddress((void**)&s_b1adj, g_b1adj);

    const size_t off_ei = (size_t)NNODES * HID;            // 6,400,000
    const size_t off_ea = off_ei + 2ULL * NEDGES;          // 8,000,000
    const size_t full = off_ea + (size_t)NEDGES * HID;     // 110,400,000
    const bool want_ei = (size_t)out_size >= off_ea;
    const bool want_ea = (size_t)out_size >= full;

    const int smem_bytes = SMEM_FLOATS * 4;  // ~135 KB
    cudaFuncSetAttribute(mlp_fused_kernel,
                         cudaFuncAttributeMaxDynamicSharedMemorySize,
                         smem_bytes);

    init_kernel<<<64, 256>>>((const int*)edge_index);
    eidx_hist_kernel<<<1024, 256>>>(edge_index,
                                    want_ei ? (out + off_ei) : nullptr);
    scan1_kernel<<<SNB, SB>>>();
    scan2_kernel<<<1, 128>>>();
    scan3_kernel<<<SNB, SB>>>();
    fill_kernel<<<1024, 256>>>(edge_index);
    gather_kernel<<<NNODES / 8, 256>>>(edge_attr,
                                       want_ea ? (out + off_ea) : nullptr);
    b1adj_kernel<<<1, 128>>>(W1, b1);

    const int mblocks = (NNODES + 127) / 128;  // 391
    mlp_fused_kernel<<<mblocks, 256, smem_bytes>>>(node_attr, s_agg, W1,
                                                   s_b1adj, W2, b2, out);
}

// round 14
// speedup vs baseline: 1.0093x; 1.0093x over previous
#include <cuda_runtime.h>
#include <cstdint>

#define NNODES 50000
#define NEDGES 800000
#define HID 128

#define SB 512
#define SNB ((NNODES + SB - 1) / SB)  // 98

__device__ float g_agg[(size_t)NNODES * HID];
__device__ float g_colsum[HID];
__device__ float g_b1adj[HID];
__device__ int g_is64;              // 1 if edge_index is int64
__device__ int g_deg[NNODES];       // receiver degree histogram
__device__ int g_off[NNODES];       // LOCAL exclusive offsets (within 512-block)
__device__ int g_cursor[NNODES];    // fill cursors (local)
__device__ int g_perm[NEDGES];      // edge ids grouped by receiver
__device__ int g_bsum[SNB];         // per-block sums
__device__ int g_bprefix[SNB];      // exclusive prefix of block sums

// ---------------------------------------------------------------------------
// Fused: detect edge_index dtype (block 0) + zero g_deg/g_colsum.
// ---------------------------------------------------------------------------
__global__ void init_kernel(const int* __restrict__ ei32) {
    if (blockIdx.x == 0) {
        __shared__ int nz;
        if (threadIdx.x == 0) nz = 0;
        __syncthreads();
        int cnt = 0;
        for (int i = threadIdx.x; i < 1024; i += blockDim.x)
            if (ei32[2 * i + 1] != 0) cnt++;
        atomicAdd(&nz, cnt);
        __syncthreads();
        if (threadIdx.x == 0) g_is64 = (nz == 0) ? 1 : 0;
        if (threadIdx.x < HID) g_colsum[threadIdx.x] = 0.0f;
    }
    for (int i = blockIdx.x * blockDim.x + threadIdx.x; i < NNODES;
         i += gridDim.x * blockDim.x)
        g_deg[i] = 0;
}

// ---------------------------------------------------------------------------
// Receiver histogram only (passthrough moved to side-stream copy kernel).
// ---------------------------------------------------------------------------
__global__ void hist_kernel(const void* __restrict__ ei) {
    for (int e = blockIdx.x * blockDim.x + threadIdx.x; e < NEDGES;
         e += gridDim.x * blockDim.x) {
        long long v;
        if (g_is64)
            v = ((const long long*)ei)[(size_t)NEDGES + e];
        else
            v = ((const int*)ei)[(size_t)NEDGES + e];
        if (v >= 0 && v < NNODES) atomicAdd(&g_deg[(int)v], 1);
    }
}

// ---------------------------------------------------------------------------
// edge_index -> float passthrough (independent; runs on side stream).
// ---------------------------------------------------------------------------
__global__ void eidx_copy_kernel(const void* __restrict__ ei,
                                 float* __restrict__ out) {
    int total = 2 * NEDGES;
    for (int i = blockIdx.x * blockDim.x + threadIdx.x; i < total;
         i += gridDim.x * blockDim.x) {
        long long v;
        if (g_is64)
            v = ((const long long*)ei)[i];
        else
            v = ((const int*)ei)[i];
        out[i] = (float)v;
    }
}

// ---------------------------------------------------------------------------
// scan1: local exclusive scan within each 512-block; emit block sums.
// ---------------------------------------------------------------------------
__global__ void __launch_bounds__(SB) scan1_kernel() {
    __shared__ int s[SB];
    const int b = blockIdx.x, t = threadIdx.x;
    const int i = b * SB + t;
    int v = (i < NNODES) ? g_deg[i] : 0;
    s[t] = v;
    __syncthreads();
    for (int d = 1; d < SB; d <<= 1) {
        int x = (t >= d) ? s[t - d] : 0;
        __syncthreads();
        s[t] += x;
        __syncthreads();
    }
    if (i < NNODES) {
        int loc = s[t] - v;
        g_off[i] = loc;
        g_cursor[i] = loc;
    }
    if (t == SB - 1) g_bsum[b] = s[t];
}

// scanB: tiny exclusive scan of the 98 block sums.
__global__ void __launch_bounds__(128) scanB_kernel() {
    __shared__ int sh[128];
    const int t = threadIdx.x;
    int v = (t < SNB) ? g_bsum[t] : 0;
    sh[t] = v;
    __syncthreads();
    for (int d = 1; d < 128; d <<= 1) {
        int x = (t >= d) ? sh[t - d] : 0;
        __syncthreads();
        sh[t] += x;
        __syncthreads();
    }
    if (t < SNB) g_bprefix[t] = sh[t] - v;
}

// ---------------------------------------------------------------------------
// Fill permutation: pos = bprefix[block(v)] + local cursor.
// ---------------------------------------------------------------------------
__global__ void fill_kernel(const void* __restrict__ ei) {
    for (int e = blockIdx.x * blockDim.x + threadIdx.x; e < NEDGES;
         e += gridDim.x * blockDim.x) {
        long long v;
        if (g_is64)
            v = ((const long long*)ei)[(size_t)NEDGES + e];
        else
            v = ((const int*)ei)[(size_t)NEDGES + e];
        if (v < 0 || v >= NNODES) continue;
        int n = (int)v;
        int pos = g_bprefix[n >> 9] + atomicAdd(&g_cursor[n], 1);
        g_perm[pos] = e;
    }
}

// ---------------------------------------------------------------------------
// Gather: one warp per node; no float atomics; fused passthrough + colsum.
// ---------------------------------------------------------------------------
__global__ void __launch_bounds__(256) gather_kernel(
    const float* __restrict__ edge_attr,
    float* __restrict__ out_edge_attr) {
    __shared__ float s_cs[HID];
    const int t = threadIdx.x;
    if (t < HID) s_cs[t] = 0.0f;
    __syncthreads();

    const int lane = t & 31;
    const int node = blockIdx.x * 8 + (t >> 5);

    float4 acc = make_float4(0.f, 0.f, 0.f, 0.f);
    if (node < NNODES) {
        const int start = g_bprefix[node >> 9] + g_off[node];
        const int deg = g_deg[node];
        int i = 0;
        for (; i + 2 <= deg; i += 2) {
            int e0 = g_perm[start + i];
            int e1 = g_perm[start + i + 1];
            float4 v0 = ((const float4*)(edge_attr + (size_t)e0 * HID))[lane];
            float4 v1 = ((const float4*)(edge_attr + (size_t)e1 * HID))[lane];
            if (out_edge_attr) {
                ((float4*)(out_edge_attr + (size_t)e0 * HID))[lane] = v0;
                ((float4*)(out_edge_attr + (size_t)e1 * HID))[lane] = v1;
            }
            acc.x += v0.x + v1.x;
            acc.y += v0.y + v1.y;
            acc.z += v0.z + v1.z;
            acc.w += v0.w + v1.w;
        }
        if (i < deg) {
            int e0 = g_perm[start + i];
            float4 v0 = ((const float4*)(edge_attr + (size_t)e0 * HID))[lane];
            if (out_edge_attr)
                ((float4*)(out_edge_attr + (size_t)e0 * HID))[lane] = v0;
            acc.x += v0.x;
            acc.y += v0.y;
            acc.z += v0.z;
            acc.w += v0.w;
        }
        ((float4*)(g_agg + (size_t)node * HID))[lane] = acc;
    }

    atomicAdd(&s_cs[lane * 4 + 0], acc.x);
    atomicAdd(&s_cs[lane * 4 + 1], acc.y);
    atomicAdd(&s_cs[lane * 4 + 2], acc.z);
    atomicAdd(&s_cs[lane * 4 + 3], acc.w);
    __syncthreads();
    if (t < 32) {
        float4 cv = *(float4*)&s_cs[t * 4];
        asm volatile("red.global.add.v4.f32 [%0], {%1, %2, %3, %4};"
                     :: "l"(&g_colsum[t * 4]), "f"(cv.x), "f"(cv.y), "f"(cv.z),
                        "f"(cv.w)
                     : "memory");
    }
}

// b1'[j] = b1[j] - (1/N) * sum_c colsum[c] * W1[128+c][j]
__global__ void b1adj_kernel(const float* __restrict__ W1,
                             const float* __restrict__ b1) {
    int j = threadIdx.x;
    float acc = 0.0f;
#pragma unroll 8
    for (int c = 0; c < HID; c++)
        acc = fmaf(g_colsum[c], W1[(size_t)(HID + c) * HID + j], acc);
    g_b1adj[j] = b1[j] - acc * (1.0f / (float)NNODES);
}

// ---------------------------------------------------------------------------
// Fused MLP with cp.async double buffering (unchanged from round 13).
// ---------------------------------------------------------------------------
__device__ __forceinline__ float f2tf(float x) {
    uint32_t r;
    asm("cvt.rna.tf32.f32 %0, %1;" : "=r"(r) : "f"(x));
    return __uint_as_float(r);
}

__device__ __forceinline__ uint32_t tfbits(float x) {
    uint32_t r;
    asm("cvt.rna.tf32.f32 %0, %1;" : "=r"(r) : "f"(x));
    return r;
}

__device__ __forceinline__ void mma_tf32(float* c, const uint32_t* a,
                                         const uint32_t* b) {
    asm volatile(
        "mma.sync.aligned.m16n8k8.row.col.f32.tf32.tf32.f32 "
        "{%0,%1,%2,%3}, {%4,%5,%6,%7}, {%8,%9}, {%0,%1,%2,%3};"
        : "+f"(c[0]), "+f"(c[1]), "+f"(c[2]), "+f"(c[3])
        : "r"(a[0]), "r"(a[1]), "r"(a[2]), "r"(a[3]), "r"(b[0]), "r"(b[1]));
}

__device__ __forceinline__ void cp16(uint32_t dst_smem, const void* src,
                                     int src_sz) {
    asm volatile("cp.async.cg.shared.global [%0], [%1], 16, %2;"
                 :: "r"(dst_smem), "l"(src), "r"(src_sz));
}
#define CP_COMMIT() asm volatile("cp.async.commit_group;")
#define CP_WAIT(N) asm volatile("cp.async.wait_group %0;" :: "n"(N))

#define AS_OFF(b) ((b) * 4608)
#define BS_OFF(b) (9216 + (b) * 4224)
#define HS_OFF 17664
#define SMEM_FLOATS (17664 + 128 * 132)

__global__ void __launch_bounds__(256) mlp_fused_kernel(
    const float* __restrict__ A0, const float* __restrict__ A1,
    const float* __restrict__ W1, const float* __restrict__ bias1,
    const float* __restrict__ W2, const float* __restrict__ bias2,
    float* __restrict__ C) {
    extern __shared__ float smem[];
    const uint32_t sbase = (uint32_t)__cvta_generic_to_shared(smem);

    const int t = threadIdx.x;
    const int w = t >> 5, lane = t & 31;
    const int wm = w >> 2, wn = w & 3;
    const int g = lane >> 2, j = lane & 3;
    const int block_m = blockIdx.x * 128;

    const int a_row = t >> 3;
    const int a_c4 = (t & 7) * 4;
    const int b_kr = t >> 5;
    const int b_c4 = (t & 31) * 4;

    auto issue_p1 = [&](int kb, int bi) {
        const int kbase = kb * 32;
#pragma unroll
        for (int i = 0; i < 4; i++) {
            int row = a_row + i * 32;
            int gm = block_m + row;
            int k = kbase + a_c4;
            const float* src = (k < HID) ? (A0 + (size_t)gm * HID + k)
                                         : (A1 + (size_t)gm * HID + (k - HID));
            cp16(sbase + (AS_OFF(bi) + row * 36 + a_c4) * 4, src,
                 (gm < NNODES) ? 16 : 0);
        }
#pragma unroll
        for (int i = 0; i < 4; i++) {
            int kr = b_kr + i * 8;
            cp16(sbase + (BS_OFF(bi) + kr * 132 + b_c4) * 4,
                 W1 + (size_t)(kbase + kr) * HID + b_c4, 16);
        }
        CP_COMMIT();
    };

    float(*Hs)[132] = (float(*)[132])(smem + HS_OFF);

    {
        float acc[4][4][4] = {};
        issue_p1(0, 0);
        for (int kb = 0; kb < 8; kb++) {
            const int bi = kb & 1;
            if (kb + 1 < 8) {
                issue_p1(kb + 1, (kb + 1) & 1);
                CP_WAIT(1);
            } else {
                CP_WAIT(0);
            }
            __syncthreads();

            const float* As = smem + AS_OFF(bi);
            const float* Bs = smem + BS_OFF(bi);
#pragma unroll
            for (int kk = 0; kk < 4; kk++) {
                const int k0 = kk * 8;
                uint32_t bf[4][2];
#pragma unroll
                for (int nt = 0; nt < 4; nt++) {
                    int n0 = wn * 32 + nt * 8 + g;
                    bf[nt][0] = tfbits(Bs[(k0 + j) * 132 + n0]);
                    bf[nt][1] = tfbits(Bs[(k0 + j + 4) * 132 + n0]);
                }
#pragma unroll
                for (int mt = 0; mt < 4; mt++) {
                    int m0 = wm * 64 + mt * 16;
                    uint32_t af[4];
                    af[0] = tfbits(As[(m0 + g) * 36 + k0 + j]);
                    af[1] = tfbits(As[(m0 + g + 8) * 36 + k0 + j]);
                    af[2] = tfbits(As[(m0 + g) * 36 + k0 + j + 4]);
                    af[3] = tfbits(As[(m0 + g + 8) * 36 + k0 + j + 4]);
#pragma unroll
                    for (int nt = 0; nt < 4; nt++)
                        mma_tf32(acc[mt][nt], af, bf[nt]);
                }
            }
            __syncthreads();
        }

#pragma unroll
        for (int mt = 0; mt < 4; mt++) {
#pragma unroll
            for (int half = 0; half < 2; half++) {
                int row = wm * 64 + mt * 16 + g + half * 8;
#pragma unroll
                for (int nt = 0; nt < 4; nt++) {
                    int n = wn * 32 + nt * 8 + 2 * j;
                    float x0 = acc[mt][nt][half * 2 + 0] + bias1[n + 0];
                    float x1 = acc[mt][nt][half * 2 + 1] + bias1[n + 1];
                    Hs[row][n] = f2tf(fmaxf(x0, 0.f));
                    Hs[row][n + 1] = f2tf(fmaxf(x1, 0.f));
                }
            }
        }
        __syncthreads();
    }

    auto issue_p2 = [&](int kb, int bi) {
        const int kbase = kb * 32;
#pragma unroll
        for (int i = 0; i < 4; i++) {
            int kr = b_kr + i * 8;
            cp16(sbase + (BS_OFF(bi) + kr * 132 + b_c4) * 4,
                 W2 + (size_t)(kbase + kr) * HID + b_c4, 16);
        }
        CP_COMMIT();
    };

    {
        float acc[4][4][4] = {};
        issue_p2(0, 0);
        for (int kb = 0; kb < 4; kb++) {
            const int bi = kb & 1;
            if (kb + 1 < 4) {
                issue_p2(kb + 1, (kb + 1) & 1);
                CP_WAIT(1);
            } else {
                CP_WAIT(0);
            }
            __syncthreads();

            const float* Bs = smem + BS_OFF(bi);
            const int kbase = kb * 32;
#pragma unroll
            for (int kk = 0; kk < 4; kk++) {
                const int k0 = kbase + kk * 8;
                uint32_t bf[4][2];
#pragma unroll
                for (int nt = 0; nt < 4; nt++) {
                    int n0 = wn * 32 + nt * 8 + g;
                    bf[nt][0] = tfbits(Bs[(kk * 8 + j) * 132 + n0]);
                    bf[nt][1] = tfbits(Bs[(kk * 8 + j + 4) * 132 + n0]);
                }
#pragma unroll
                for (int mt = 0; mt < 4; mt++) {
                    int m0 = wm * 64 + mt * 16;
                    uint32_t af[4];
                    af[0] = __float_as_uint(Hs[m0 + g][k0 + j]);
                    af[1] = __float_as_uint(Hs[m0 + g + 8][k0 + j]);
                    af[2] = __float_as_uint(Hs[m0 + g][k0 + j + 4]);
                    af[3] = __float_as_uint(Hs[m0 + g + 8][k0 + j + 4]);
#pragma unroll
                    for (int nt = 0; nt < 4; nt++)
                        mma_tf32(acc[mt][nt], af, bf[nt]);
                }
            }
            __syncthreads();
        }

#pragma unroll
        for (int mt = 0; mt < 4; mt++) {
#pragma unroll
            for (int half = 0; half < 2; half++) {
                int gm = block_m + wm * 64 + mt * 16 + g + half * 8;
                if (gm >= NNODES) continue;
#pragma unroll
                for (int nt = 0; nt < 4; nt++) {
                    int n = wn * 32 + nt * 8 + 2 * j;
                    float2 v;
                    v.x = acc[mt][nt][half * 2 + 0] + bias2[n + 0];
                    v.y = acc[mt][nt][half * 2 + 1] + bias2[n + 1];
                    *(float2*)(C + (size_t)gm * HID + n) = v;
                }
            }
        }
    }
}

extern "C" void kernel_launch(void* const* d_in, const int* in_sizes, int n_in,
                              void* d_out, int out_size) {
    const float* node_attr = (const float*)d_in[0];
    const void* edge_index = d_in[1];
    const float* edge_attr = (const float*)d_in[2];
    const float* W1 = (const float*)d_in[3];
    const float* b1 = (const float*)d_in[4];
    const float* W2 = (const float*)d_in[5];
    const float* b2 = (const float*)d_in[6];
    float* out = (float*)d_out;

    float *s_agg, *s_b1adj;
    cudaGetSymbolAddress((void**)&s_agg, g_agg);
    cudaGetSymbolAddress((void**)&s_b1adj, g_b1adj);

    const size_t off_ei = (size_t)NNODES * HID;            // 6,400,000
    const size_t off_ea = off_ei + 2ULL * NEDGES;          // 8,000,000
    const size_t full = off_ea + (size_t)NEDGES * HID;     // 110,400,000
    const bool want_ei = (size_t)out_size >= off_ea;
    const bool want_ea = (size_t)out_size >= full;

    const int smem_bytes = SMEM_FLOATS * 4;  // ~135 KB
    cudaFuncSetAttribute(mlp_fused_kernel,
                         cudaFuncAttributeMaxDynamicSharedMemorySize,
                         smem_bytes);

    // Side-stream resources (created once, on the non-captured first call).
    static cudaStream_t sB = nullptr;
    static cudaEvent_t evF = nullptr, evJ = nullptr;
    if (!sB) {
        cudaStreamCreateWithFlags(&sB, cudaStreamNonBlocking);
        cudaEventCreateWithFlags(&evF, cudaEventDisableTiming);
        cudaEventCreateWithFlags(&evJ, cudaEventDisableTiming);
    }

    init_kernel<<<64, 256>>>((const int*)edge_index);

    // Fork: edge_index float passthrough runs concurrently with the
    // hist/scan/fill prepass (depends only on g_is64 set by init_kernel).
    if (want_ei) {
        cudaEventRecord(evF, 0);
        cudaStreamWaitEvent(sB, evF, 0);
        eidx_copy_kernel<<<512, 256, 0, sB>>>(edge_index, out + off_ei);
        cudaEventRecord(evJ, sB);
    }

    hist_kernel<<<1024, 256>>>(edge_index);
    scan1_kernel<<<SNB, SB>>>();
    scanB_kernel<<<1, 128>>>();
    fill_kernel<<<1024, 256>>>(edge_index);
    gather_kernel<<<NNODES / 8, 256>>>(edge_attr,
                                       want_ea ? (out + off_ea) : nullptr);
    b1adj_kernel<<<1, 128>>>(W1, b1);

    const int mblocks = (NNODES + 127) / 128;  // 391
    mlp_fused_kernel<<<mblocks, 256, smem_bytes>>>(node_attr, s_agg, W1,
                                                   s_b1adj, W2, b2, out);

    // Join the side stream back into the main stream.
    if (want_ei) cudaStreamWaitEvent(0, evJ, 0);
}